// round 15
// baseline (speedup 1.0000x reference)
#include <cuda_runtime.h>
#include <cuda_bf16.h>
#include <cstdint>

// ----------------------------------------------------------------------------
// Shapes: N=50000, K=16 neighbors, IN=128, T2V=64, F=IN+T2V=192, H=128
// Pipeline:
//   prep      : M=(Wq1 Wk^T)/sqrt(H), c, Wvo=Wv Wo -> bf16 hi/lo B^T planes
//   convert_x : x -> bf16 hi/lo planes
//   gemm1     : A = x @ M + c            (HMMA 2-split, cp.async, persistent)
//   attn      : warp/node single pass, unshifted softmax -> H hi/lo planes
//   gemm2     : out = relu(H @ Wvo + bo) (HMMA 2-split, cp.async, persistent)
// ----------------------------------------------------------------------------
#define KNBR 16
#define INF  128
#define T2VD 64
#define FD   192
#define HD   128
#define NMAX 50176

__device__ float g_c[FD];
__device__ __align__(16) float g_A[(size_t)NMAX * FD];
__device__ __align__(16) __nv_bfloat16 g_Xhi[(size_t)NMAX * INF];
__device__ __align__(16) __nv_bfloat16 g_Xlo[(size_t)NMAX * INF];
__device__ __align__(16) __nv_bfloat16 g_Hhi[(size_t)NMAX * FD];
__device__ __align__(16) __nv_bfloat16 g_Hlo[(size_t)NMAX * FD];
__device__ __align__(16) __nv_bfloat16 g_B1hi[FD * INF];
__device__ __align__(16) __nv_bfloat16 g_B1lo[FD * INF];
__device__ __align__(16) __nv_bfloat16 g_B2hi[HD * FD];
__device__ __align__(16) __nv_bfloat16 g_B2lo[HD * FD];

// ============================ helpers =======================================
__device__ __forceinline__ uint32_t smem_u32(const void* p) {
    uint32_t a;
    asm("{ .reg .u64 t; cvta.to.shared.u64 t, %1; cvt.u32.u64 %0, t; }"
        : "=r"(a) : "l"(p));
    return a;
}
__device__ __forceinline__ uint32_t bf2pack(float lo, float hi) {
    uint32_t r;
    asm("cvt.rn.bf16x2.f32 %0, %1, %2;" : "=r"(r) : "f"(hi), "f"(lo));
    return r;
}
__device__ __forceinline__ void split2(float v0, float v1, uint32_t& hp, uint32_t& lp) {
    hp = bf2pack(v0, v1);
    float h0 = __uint_as_float(hp << 16);
    float h1 = __uint_as_float(hp & 0xFFFF0000u);
    lp = bf2pack(v0 - h0, v1 - h1);
}
#define LDSM4(r, addr) \
    asm volatile("ldmatrix.sync.aligned.m8n8.x4.shared.b16 {%0,%1,%2,%3}, [%4];" \
        : "=r"((r)[0]), "=r"((r)[1]), "=r"((r)[2]), "=r"((r)[3]) : "r"(addr))
#define MMA_BF16(d, a, b0_, b1_) \
    asm volatile("mma.sync.aligned.m16n8k16.row.col.f32.bf16.bf16.f32 " \
        "{%0,%1,%2,%3}, {%4,%5,%6,%7}, {%8,%9}, {%0,%1,%2,%3};" \
        : "+f"((d)[0]), "+f"((d)[1]), "+f"((d)[2]), "+f"((d)[3]) \
        : "r"((a)[0]), "r"((a)[1]), "r"((a)[2]), "r"((a)[3]), "r"(b0_), "r"(b1_))
#define CP_ASYNC16(dst, src) \
    asm volatile("cp.async.cg.shared.global [%0], [%1], 16;" :: "r"(dst), "l"(src))
#define CP_COMMIT() asm volatile("cp.async.commit_group;" ::: "memory")
#define CP_WAIT(n)  asm volatile("cp.async.wait_group %0;" :: "n"(n) : "memory")

// ============================ prep ==========================================
#define WQS 129
__global__ void prep_kernel(const float* __restrict__ Wq, const float* __restrict__ Wk,
                            const float* __restrict__ Wv, const float* __restrict__ Wo,
                            const float* __restrict__ w0, const float* __restrict__ b0,
                            const float* __restrict__ Wt, const float* __restrict__ Bt)
{
    extern __shared__ float sWq[];     // 128 x 129 floats
    __shared__ float wkrow[HD];
    __shared__ float wvrow[HD];
    __shared__ float tev[T2VD];
    __shared__ float red[HD];

    const int f = blockIdx.x;   // 0..191
    const int t = threadIdx.x;  // 0..127

    for (int i = t; i < INF * (INF / 4); i += HD) {
        const int r = i / (INF / 4);
        const int c4 = i % (INF / 4);
        const float4 v = *(const float4*)(Wq + (size_t)r * HD + c4 * 4);
        float* dst = sWq + r * WQS + c4 * 4;
        dst[0] = v.x; dst[1] = v.y; dst[2] = v.z; dst[3] = v.w;
    }
    wkrow[t] = Wk[f * HD + t];
    wvrow[t] = Wv[f * HD + t];
    if (t < T2VD) tev[t] = (t == 0) ? b0[0] : sinf(Bt[t - 1]);   // time2vec(0)
    __syncthreads();

    const float scale = 0.08838834764831845f;  // 1/sqrt(128)

    float m = 0.f;
    #pragma unroll 8
    for (int h = 0; h < HD; h++) m = fmaf(sWq[t * WQS + h], wkrow[h], m);
    m *= scale;
    {
        __nv_bfloat16 hi = __float2bfloat16(m);
        __nv_bfloat16 lo = __float2bfloat16(m - __bfloat162float(hi));
        g_B1hi[f * INF + t] = hi;
        g_B1lo[f * INF + t] = lo;
    }

    float wv = 0.f;
    #pragma unroll 4
    for (int h = 0; h < HD; h++) wv = fmaf(wvrow[h], Wo[h * HD + t], wv);
    {
        __nv_bfloat16 hi = __float2bfloat16(wv);
        __nv_bfloat16 lo = __float2bfloat16(wv - __bfloat162float(hi));
        g_B2hi[t * FD + f] = hi;
        g_B2lo[t * FD + f] = lo;
    }

    float qc = 0.f;
    #pragma unroll 4
    for (int j = 0; j < T2VD; j++) qc = fmaf(tev[j], Wq[(INF + j) * HD + t], qc);
    red[t] = qc * wkrow[t];
    __syncthreads();
    for (int s = 64; s > 0; s >>= 1) {
        if (t < s) red[t] += red[t + s];
        __syncthreads();
    }
    if (t == 0) g_c[f] = red[0] * scale;
}

// ============================ convert x -> hi/lo planes =====================
__global__ __launch_bounds__(256)
void convert_x(const float* __restrict__ x, int count4)
{
    const int i = blockIdx.x * 256 + threadIdx.x;
    if (i >= count4) return;
    const float4 v = ((const float4*)x)[i];
    uint32_t h0, l0, h1, l1;
    split2(v.x, v.y, h0, l0);
    split2(v.z, v.w, h1, l1);
    ((uint2*)g_Xhi)[i] = make_uint2(h0, h1);
    ((uint2*)g_Xlo)[i] = make_uint2(l0, l1);
}

// ============================ HMMA GEMM (persistent, cp.async) ==============
// C[n, 0..JD) = act( sum_k A[n,k]*B[j,k] + bias[j] ), A & B as bf16 hi/lo planes.
// CTA tile 128x64, BK=32 chunks, 2-stage cp.async double buffer, 3 CTAs/SM.
// Persistent: grid = 444 CTAs, each strides over all tiles (kills wave tail).
template<int KD, int JD, int RELU>
__global__ __launch_bounds__(256, 3)
void mma_gemm(const __nv_bfloat16* __restrict__ Ahi, const __nv_bfloat16* __restrict__ Alo,
              const __nv_bfloat16* __restrict__ Bhi, const __nv_bfloat16* __restrict__ Blo,
              const float* __restrict__ bias, float* __restrict__ C, int Nrows)
{
    constexpr int BK     = 32;
    constexpr int NC     = KD / BK;
    constexpr int JT     = JD / 64;
    constexpr int ABYTES = 128 * BK * 2;              // 8192 per plane
    constexpr int BBYTES = 64 * BK * 2;               // 4096 per plane
    constexpr int STAGE  = 2 * ABYTES + 2 * BBYTES;   // 24576

    extern __shared__ __align__(16) char smem[];
    const uint32_t sbase = smem_u32(smem);

    const int tid   = threadIdx.x;
    const int lane  = tid & 31;
    const int wid   = tid >> 5;
    const int wm    = wid & 3;
    const int wn    = wid >> 2;
    const uint32_t swA = (uint32_t)(((lane & 15) >> 1) & 3);
    const uint32_t swB = (uint32_t)(((lane & 7) >> 1) & 3);
    const uint32_t aDg = (uint32_t)(lane >> 4);
    const uint32_t bDg = (uint32_t)((lane >> 3) & 1);

    uint32_t aOff[2], bOff[2];
    #pragma unroll
    for (int mt = 0; mt < 2; mt++)
        aOff[mt] = (uint32_t)((wm * 32 + mt * 16 + (lane & 15)) * 64);
    #pragma unroll
    for (int np = 0; np < 2; np++)
        bOff[np] = (uint32_t)((wn * 32 + np * 16 + (lane & 7) + ((lane >> 4) << 3)) * 64);

    const int total = JT * ((Nrows + 127) / 128);

    for (int tile = blockIdx.x; tile < total; tile += gridDim.x) {
        const int j0   = (tile % JT) * 64;
        const int row0 = (tile / JT) * 128;

        auto load_chunk = [&](int c, int s) {
            const uint32_t sst = sbase + (uint32_t)(s * STAGE);
            const int kbase = c * BK;
            #pragma unroll
            for (int it = 0; it < 2; it++) {
                const int task = tid + it * 256;          // 0..511
                const int r = task >> 2, g = task & 3;
                int sr = row0 + r; if (sr >= Nrows) sr = Nrows - 1;
                const uint32_t soff = (uint32_t)(r * 64 + (g ^ ((r >> 1) & 3)) * 16);
                const size_t gi = (size_t)sr * KD + kbase + g * 8;
                CP_ASYNC16(sst + soff,          (const char*)(Ahi + gi));
                CP_ASYNC16(sst + ABYTES + soff, (const char*)(Alo + gi));
            }
            {
                const int r = tid >> 2, g = tid & 3;
                const uint32_t soff = (uint32_t)(r * 64 + (g ^ ((r >> 1) & 3)) * 16);
                const size_t gi = (size_t)(j0 + r) * KD + kbase + g * 8;
                CP_ASYNC16(sst + 2 * ABYTES + soff,          (const char*)(Bhi + gi));
                CP_ASYNC16(sst + 2 * ABYTES + BBYTES + soff, (const char*)(Blo + gi));
            }
        };

        float acc[2][4][4];
        #pragma unroll
        for (int mt = 0; mt < 2; mt++)
            #pragma unroll
            for (int nt = 0; nt < 4; nt++)
                #pragma unroll
                for (int q = 0; q < 4; q++) acc[mt][nt][q] = 0.f;

        load_chunk(0, 0);
        CP_COMMIT();

        #pragma unroll
        for (int c = 0; c < NC; c++) {
            if (c + 1 < NC) {
                load_chunk(c + 1, (c + 1) & 1);
                CP_COMMIT();
                CP_WAIT(1);
            } else {
                CP_WAIT(0);
            }
            __syncthreads();

            const uint32_t sA = sbase + (uint32_t)((c & 1) * STAGE);
            const uint32_t sB = sA + 2 * ABYTES;
            #pragma unroll
            for (int ks = 0; ks < BK / 16; ks++) {
                const uint32_t kg = 2 * ks;
                uint32_t ah[2][4], al[2][4], bh[2][4], bl[2][4];
                #pragma unroll
                for (int mt = 0; mt < 2; mt++) {
                    const uint32_t addr = sA + aOff[mt] + ((kg + aDg) ^ swA) * 16u;
                    LDSM4(ah[mt], addr);
                    LDSM4(al[mt], addr + (uint32_t)ABYTES);
                }
                #pragma unroll
                for (int np = 0; np < 2; np++) {
                    const uint32_t addr = sB + bOff[np] + ((kg + bDg) ^ swB) * 16u;
                    LDSM4(bh[np], addr);
                    LDSM4(bl[np], addr + (uint32_t)BBYTES);
                }
                #pragma unroll
                for (int mt = 0; mt < 2; mt++)
                    #pragma unroll
                    for (int np = 0; np < 2; np++)
                        #pragma unroll
                        for (int h = 0; h < 2; h++) {
                            float* d = acc[mt][np * 2 + h];
                            MMA_BF16(d, ah[mt], bh[np][2 * h], bh[np][2 * h + 1]);
                            MMA_BF16(d, al[mt], bh[np][2 * h], bh[np][2 * h + 1]);
                            MMA_BF16(d, ah[mt], bl[np][2 * h], bl[np][2 * h + 1]);
                        }
            }
            __syncthreads();
        }

        const int g  = lane >> 2;
        const int tg = lane & 3;
        #pragma unroll
        for (int nt = 0; nt < 4; nt++) {
            const int col = j0 + wn * 32 + nt * 8 + tg * 2;
            const float b0 = bias[col], b1 = bias[col + 1];
            #pragma unroll
            for (int mt = 0; mt < 2; mt++) {
                const float* d = acc[mt][nt];
                const int r0 = row0 + wm * 32 + mt * 16 + g;
                if (r0 < Nrows) {
                    float2 v = make_float2(d[0] + b0, d[1] + b1);
                    if (RELU) { v.x = fmaxf(v.x, 0.f); v.y = fmaxf(v.y, 0.f); }
                    *(float2*)(C + (size_t)r0 * JD + col) = v;
                }
                const int r1 = r0 + 8;
                if (r1 < Nrows) {
                    float2 v = make_float2(d[2] + b0, d[3] + b1);
                    if (RELU) { v.x = fmaxf(v.x, 0.f); v.y = fmaxf(v.y, 0.f); }
                    *(float2*)(C + (size_t)r1 * JD + col) = v;
                }
            }
        }
        // epilogue reads registers only; next tile's stage-0 write is safe
        // (stage 0 was last read two syncs ago).
    }
}

// ============================ attention =====================================
// One warp per node, single pass, no smem, unshifted softmax (|p| small).
// Exact R11 loop (best measured attention variant).
// Output H written directly as pre-split bf16 hi/lo planes for GEMM2.
__global__ __launch_bounds__(256)
void attn_kernel(const float* __restrict__ x, const float* __restrict__ ts,
                 const int* __restrict__ idx,
                 const float* __restrict__ w0p, const float* __restrict__ b0p,
                 const float* __restrict__ Wt, const float* __restrict__ Bt,
                 const float* __restrict__ A, int N)
{
    const int wid  = threadIdx.x >> 5;
    const int lane = threadIdx.x & 31;
    const int n    = blockIdx.x * 8 + wid;
    if (n >= N) return;

    int   m_l = 0;
    float t_l = 0.f;
    if (lane < KNBR) {
        m_l = idx[n * KNBR + lane];
        t_l = ts [n * KNBR + lane];
    }

    const float* Arow = A + (size_t)n * FD;
    const float4 aX  = *(const float4*)(Arow + lane * 4);
    const float  aT0 = Arow[INF + lane];
    const float  aT1 = Arow[INF + 32 + lane];

    float w_a, b_a;
    if (lane == 0) { w_a = w0p[0]; b_a = b0p[0]; }
    else           { w_a = Wt[lane - 1]; b_a = Bt[lane - 1]; }
    const float w_b = Wt[lane + 31];
    const float b_b = Bt[lane + 31];

    float lsum = 0.f;
    float4 acc = make_float4(0.f, 0.f, 0.f, 0.f);
    float at0 = 0.f, at1 = 0.f;

    #pragma unroll
    for (int k = 0; k < KNBR; k++) {
        const int   m = __shfl_sync(0xffffffffu, m_l, k);
        const float t = __shfl_sync(0xffffffffu, t_l, k);
        const float4 xv = *(const float4*)(x + (size_t)m * INF + lane * 4);

        float va = fmaf(t, w_a, b_a);
        if (lane != 0) va = __sinf(va);
        const float vb = __sinf(fmaf(t, w_b, b_b));

        float p = xv.x * aX.x;
        p = fmaf(xv.y, aX.y, p);
        p = fmaf(xv.z, aX.z, p);
        p = fmaf(xv.w, aX.w, p);
        p = fmaf(va, aT0, p);
        p = fmaf(vb, aT1, p);
        #pragma unroll
        for (int o = 16; o > 0; o >>= 1) p += __shfl_xor_sync(0xffffffffu, p, o);

        const float e = __expf(p);   // |p| small: no max shift needed
        lsum += e;
        acc.x = fmaf(e, xv.x, acc.x);
        acc.y = fmaf(e, xv.y, acc.y);
        acc.z = fmaf(e, xv.z, acc.z);
        acc.w = fmaf(e, xv.w, acc.w);
        at0 = fmaf(e, va, at0);
        at1 = fmaf(e, vb, at1);
    }

    const float inv = 1.0f / lsum;
    __nv_bfloat16* hh = g_Hhi + (size_t)n * FD;
    __nv_bfloat16* hl = g_Hlo + (size_t)n * FD;

    uint32_t h0, l0, h1, l1;
    split2(acc.x * inv, acc.y * inv, h0, l0);
    split2(acc.z * inv, acc.w * inv, h1, l1);
    *(uint2*)(hh + lane * 4) = make_uint2(h0, h1);
    *(uint2*)(hl + lane * 4) = make_uint2(l0, l1);

    {
        const float v0 = at0 * inv;
        const __nv_bfloat16 hv = __float2bfloat16(v0);
        hh[INF + lane] = hv;
        hl[INF + lane] = __float2bfloat16(v0 - __bfloat162float(hv));
    }
    {
        const float v1 = at1 * inv;
        const __nv_bfloat16 hv = __float2bfloat16(v1);
        hh[INF + 32 + lane] = hv;
        hl[INF + 32 + lane] = __float2bfloat16(v1 - __bfloat162float(hv));
    }
}

// ============================ launch ========================================
// Input order: x, ts, idx, t2v_w0, t2v_b0, t2v_W, t2v_B, Wq, Wk, Wv, Wo, bo
extern "C" void kernel_launch(void* const* d_in, const int* in_sizes, int n_in,
                              void* d_out, int out_size)
{
    const float* x   = (const float*)d_in[0];
    const float* ts  = (const float*)d_in[1];
    const int*   idx = (const int*)  d_in[2];
    const float* w0  = (const float*)d_in[3];
    const float* b0  = (const float*)d_in[4];
    const float* Wt  = (const float*)d_in[5];
    const float* Bt  = (const float*)d_in[6];
    const float* Wq  = (const float*)d_in[7];
    const float* Wk  = (const float*)d_in[8];
    const float* Wv  = (const float*)d_in[9];
    const float* Wo  = (const float*)d_in[10];
    const float* bo  = (const float*)d_in[11];
    float* out = (float*)d_out;

    const int N = in_sizes[0] / INF;

    void *pC, *pA, *pXh, *pXl, *pHh, *pHl, *pB1h, *pB1l, *pB2h, *pB2l;
    cudaGetSymbolAddress(&pC,   g_c);
    cudaGetSymbolAddress(&pA,   g_A);
    cudaGetSymbolAddress(&pXh,  g_Xhi);
    cudaGetSymbolAddress(&pXl,  g_Xlo);
    cudaGetSymbolAddress(&pHh,  g_Hhi);
    cudaGetSymbolAddress(&pHl,  g_Hlo);
    cudaGetSymbolAddress(&pB1h, g_B1hi);
    cudaGetSymbolAddress(&pB1l, g_B1lo);
    cudaGetSymbolAddress(&pB2h, g_B2hi);
    cudaGetSymbolAddress(&pB2l, g_B2lo);

    const int SMEM  = 2 * (2 * (128 * 32 * 2) + 2 * (64 * 32 * 2));  // 49152
    const int PSMEM = INF * WQS * 4;                                 // 66048
    const int PERSIST = 148 * 3;                                     // 444 CTAs
    cudaFuncSetAttribute(mma_gemm<128, 192, 0>,
                         cudaFuncAttributeMaxDynamicSharedMemorySize, SMEM);
    cudaFuncSetAttribute(mma_gemm<192, 128, 1>,
                         cudaFuncAttributeMaxDynamicSharedMemorySize, SMEM);
    cudaFuncSetAttribute(prep_kernel,
                         cudaFuncAttributeMaxDynamicSharedMemorySize, PSMEM);

    // 1) prep + x pre-split
    prep_kernel<<<FD, HD, PSMEM>>>(Wq, Wk, Wv, Wo, w0, b0, Wt, Bt);
    {
        const int count4 = N * (INF / 4);
        convert_x<<<(count4 + 255) / 256, 256>>>(x, count4);
    }

    // 2) A = x @ M + c        (128->192, HMMA cp.async, persistent)
    mma_gemm<128, 192, 0><<<PERSIST, 256, SMEM>>>(
        (const __nv_bfloat16*)pXh, (const __nv_bfloat16*)pXl,
        (const __nv_bfloat16*)pB1h, (const __nv_bfloat16*)pB1l,
        (const float*)pC, (float*)pA, N);

    // 3) attention -> H planes (warp per node, 8 nodes/CTA)
    attn_kernel<<<(N + 7) / 8, 256>>>(x, ts, idx, w0, b0, Wt, Bt,
                                      (const float*)pA, N);

    // 4) out = relu(H @ Wvo + bo)   (192->128, HMMA cp.async, persistent)
    mma_gemm<192, 128, 1><<<PERSIST, 256, SMEM>>>(
        (const __nv_bfloat16*)pHh, (const __nv_bfloat16*)pHl,
        (const __nv_bfloat16*)pB2h, (const __nv_bfloat16*)pB2l,
        bo, out, N);
}

// round 16
// speedup vs baseline: 1.0897x; 1.0897x over previous
#include <cuda_runtime.h>
#include <cuda_bf16.h>
#include <cstdint>

// ----------------------------------------------------------------------------
// Shapes: N=50000, K=16 neighbors, IN=128, T2V=64, F=IN+T2V=192, H=128
// Pipeline:
//   init      : FUSED prep (weight products -> bf16 hi/lo planes, bias c)
//               + convert_x (x -> bf16 hi/lo planes). Independent work on
//               disjoint CTA ranges; one launch fills the chip.
//   gemm1     : A = x @ M + c            (HMMA 2-split, cp.async 2-stage)
//   attn      : warp/node single pass, unshifted softmax -> H hi/lo planes
//   gemm2     : out = relu(H @ Wvo + bo) (HMMA 2-split, cp.async 2-stage)
// ----------------------------------------------------------------------------
#define KNBR 16
#define INF  128
#define T2VD 64
#define FD   192
#define HD   128
#define NMAX 50176

__device__ float g_c[FD];
__device__ __align__(16) float g_A[(size_t)NMAX * FD];
__device__ __align__(16) __nv_bfloat16 g_Xhi[(size_t)NMAX * INF];
__device__ __align__(16) __nv_bfloat16 g_Xlo[(size_t)NMAX * INF];
__device__ __align__(16) __nv_bfloat16 g_Hhi[(size_t)NMAX * FD];
__device__ __align__(16) __nv_bfloat16 g_Hlo[(size_t)NMAX * FD];
__device__ __align__(16) __nv_bfloat16 g_B1hi[FD * INF];
__device__ __align__(16) __nv_bfloat16 g_B1lo[FD * INF];
__device__ __align__(16) __nv_bfloat16 g_B2hi[HD * FD];
__device__ __align__(16) __nv_bfloat16 g_B2lo[HD * FD];

// ============================ helpers =======================================
__device__ __forceinline__ uint32_t smem_u32(const void* p) {
    uint32_t a;
    asm("{ .reg .u64 t; cvta.to.shared.u64 t, %1; cvt.u32.u64 %0, t; }"
        : "=r"(a) : "l"(p));
    return a;
}
__device__ __forceinline__ uint32_t bf2pack(float lo, float hi) {
    uint32_t r;
    asm("cvt.rn.bf16x2.f32 %0, %1, %2;" : "=r"(r) : "f"(hi), "f"(lo));
    return r;
}
__device__ __forceinline__ void split2(float v0, float v1, uint32_t& hp, uint32_t& lp) {
    hp = bf2pack(v0, v1);
    float h0 = __uint_as_float(hp << 16);
    float h1 = __uint_as_float(hp & 0xFFFF0000u);
    lp = bf2pack(v0 - h0, v1 - h1);
}
#define LDSM4(r, addr) \
    asm volatile("ldmatrix.sync.aligned.m8n8.x4.shared.b16 {%0,%1,%2,%3}, [%4];" \
        : "=r"((r)[0]), "=r"((r)[1]), "=r"((r)[2]), "=r"((r)[3]) : "r"(addr))
#define MMA_BF16(d, a, b0_, b1_) \
    asm volatile("mma.sync.aligned.m16n8k16.row.col.f32.bf16.bf16.f32 " \
        "{%0,%1,%2,%3}, {%4,%5,%6,%7}, {%8,%9}, {%0,%1,%2,%3};" \
        : "+f"((d)[0]), "+f"((d)[1]), "+f"((d)[2]), "+f"((d)[3]) \
        : "r"((a)[0]), "r"((a)[1]), "r"((a)[2]), "r"((a)[3]), "r"(b0_), "r"(b1_))
#define CP_ASYNC16(dst, src) \
    asm volatile("cp.async.cg.shared.global [%0], [%1], 16;" :: "r"(dst), "l"(src))
#define CP_COMMIT() asm volatile("cp.async.commit_group;" ::: "memory")
#define CP_WAIT(n)  asm volatile("cp.async.wait_group %0;" :: "n"(n) : "memory")

// ============================ init (fused prep + convert_x) =================
// CTAs [0,192): prep — weight products, bias c (128 threads active pattern).
// CTAs [192,...): convert_x — each thread 4 strided float4 splits (MLP=4).
#define WQS 129
#define CONV_CTAS 3125   // 3125 * 128 * 4 float4 = 1.6M float4 = 50000*32
__global__ void init_kernel(const float* __restrict__ Wq, const float* __restrict__ Wk,
                            const float* __restrict__ Wv, const float* __restrict__ Wo,
                            const float* __restrict__ w0, const float* __restrict__ b0,
                            const float* __restrict__ Wt, const float* __restrict__ Bt,
                            const float* __restrict__ x, int count4)
{
    if (blockIdx.x >= FD) {
        // ---- convert_x part ----
        const int cb = blockIdx.x - FD;
        const int base = cb * 128 + (int)threadIdx.x;   // stride CONV_CTAS*128
        #pragma unroll
        for (int j = 0; j < 4; j++) {
            const int i = base + j * (CONV_CTAS * 128);
            if (i < count4) {
                const float4 v = ((const float4*)x)[i];
                uint32_t h0, l0, h1, l1;
                split2(v.x, v.y, h0, l0);
                split2(v.z, v.w, h1, l1);
                ((uint2*)g_Xhi)[i] = make_uint2(h0, h1);
                ((uint2*)g_Xlo)[i] = make_uint2(l0, l1);
            }
        }
        return;
    }

    // ---- prep part ----
    extern __shared__ float sWq[];     // 128 x 129 floats
    __shared__ float wkrow[HD];
    __shared__ float wvrow[HD];
    __shared__ float tev[T2VD];
    __shared__ float red[HD];

    const int f = blockIdx.x;   // 0..191
    const int t = threadIdx.x;  // 0..127

    for (int i = t; i < INF * (INF / 4); i += HD) {
        const int r = i / (INF / 4);
        const int c4 = i % (INF / 4);
        const float4 v = *(const float4*)(Wq + (size_t)r * HD + c4 * 4);
        float* dst = sWq + r * WQS + c4 * 4;
        dst[0] = v.x; dst[1] = v.y; dst[2] = v.z; dst[3] = v.w;
    }
    wkrow[t] = Wk[f * HD + t];
    wvrow[t] = Wv[f * HD + t];
    if (t < T2VD) tev[t] = (t == 0) ? b0[0] : sinf(Bt[t - 1]);   // time2vec(0)
    __syncthreads();

    const float scale = 0.08838834764831845f;  // 1/sqrt(128)

    float m = 0.f;
    #pragma unroll 8
    for (int h = 0; h < HD; h++) m = fmaf(sWq[t * WQS + h], wkrow[h], m);
    m *= scale;
    {
        __nv_bfloat16 hi = __float2bfloat16(m);
        __nv_bfloat16 lo = __float2bfloat16(m - __bfloat162float(hi));
        g_B1hi[f * INF + t] = hi;
        g_B1lo[f * INF + t] = lo;
    }

    float wv = 0.f;
    #pragma unroll 4
    for (int h = 0; h < HD; h++) wv = fmaf(wvrow[h], Wo[h * HD + t], wv);
    {
        __nv_bfloat16 hi = __float2bfloat16(wv);
        __nv_bfloat16 lo = __float2bfloat16(wv - __bfloat162float(hi));
        g_B2hi[t * FD + f] = hi;
        g_B2lo[t * FD + f] = lo;
    }

    float qc = 0.f;
    #pragma unroll 4
    for (int j = 0; j < T2VD; j++) qc = fmaf(tev[j], Wq[(INF + j) * HD + t], qc);
    red[t] = qc * wkrow[t];
    __syncthreads();
    for (int s = 64; s > 0; s >>= 1) {
        if (t < s) red[t] += red[t + s];
        __syncthreads();
    }
    if (t == 0) g_c[f] = red[0] * scale;
}

// ============================ HMMA GEMM (2-stage cp.async) ==================
// C[n, 0..JD) = act( sum_k A[n,k]*B[j,k] + bias[j] ), A & B as bf16 hi/lo planes.
// CTA tile 128x64, BK=32 chunks, 2-stage cp.async double buffer.
template<int KD, int JD, int RELU>
__global__ __launch_bounds__(256, 3)
void mma_gemm(const __nv_bfloat16* __restrict__ Ahi, const __nv_bfloat16* __restrict__ Alo,
              const __nv_bfloat16* __restrict__ Bhi, const __nv_bfloat16* __restrict__ Blo,
              const float* __restrict__ bias, float* __restrict__ C, int Nrows)
{
    constexpr int BK     = 32;
    constexpr int NC     = KD / BK;
    constexpr int ABYTES = 128 * BK * 2;              // 8192 per plane
    constexpr int BBYTES = 64 * BK * 2;               // 4096 per plane
    constexpr int STAGE  = 2 * ABYTES + 2 * BBYTES;   // 24576

    extern __shared__ __align__(16) char smem[];
    const uint32_t sbase = smem_u32(smem);

    const int tid  = threadIdx.x;
    const int row0 = blockIdx.y * 128;
    const int j0   = blockIdx.x * 64;

    auto load_chunk = [&](int c, int s) {
        const uint32_t sst = sbase + (uint32_t)(s * STAGE);
        const int kbase = c * BK;
        #pragma unroll
        for (int it = 0; it < 2; it++) {
            const int task = tid + it * 256;          // 0..511
            const int r = task >> 2, g = task & 3;
            int sr = row0 + r; if (sr >= Nrows) sr = Nrows - 1;
            const uint32_t soff = (uint32_t)(r * 64 + (g ^ ((r >> 1) & 3)) * 16);
            const size_t gi = (size_t)sr * KD + kbase + g * 8;
            CP_ASYNC16(sst + soff,          (const char*)(Ahi + gi));
            CP_ASYNC16(sst + ABYTES + soff, (const char*)(Alo + gi));
        }
        {
            const int r = tid >> 2, g = tid & 3;
            const uint32_t soff = (uint32_t)(r * 64 + (g ^ ((r >> 1) & 3)) * 16);
            const size_t gi = (size_t)(j0 + r) * KD + kbase + g * 8;
            CP_ASYNC16(sst + 2 * ABYTES + soff,          (const char*)(Bhi + gi));
            CP_ASYNC16(sst + 2 * ABYTES + BBYTES + soff, (const char*)(Blo + gi));
        }
    };

    const int lane = tid & 31;
    const int wid  = tid >> 5;
    const int wm   = wid & 3;
    const int wn   = wid >> 2;
    const uint32_t swA = (uint32_t)(((lane & 15) >> 1) & 3);
    const uint32_t swB = (uint32_t)(((lane & 7) >> 1) & 3);
    const uint32_t aDg = (uint32_t)(lane >> 4);
    const uint32_t bDg = (uint32_t)((lane >> 3) & 1);

    uint32_t aOff[2], bOff[2];
    #pragma unroll
    for (int mt = 0; mt < 2; mt++)
        aOff[mt] = (uint32_t)((wm * 32 + mt * 16 + (lane & 15)) * 64);
    #pragma unroll
    for (int np = 0; np < 2; np++)
        bOff[np] = (uint32_t)((wn * 32 + np * 16 + (lane & 7) + ((lane >> 4) << 3)) * 64);

    float acc[2][4][4];
    #pragma unroll
    for (int mt = 0; mt < 2; mt++)
        #pragma unroll
        for (int nt = 0; nt < 4; nt++)
            #pragma unroll
            for (int q = 0; q < 4; q++) acc[mt][nt][q] = 0.f;

    load_chunk(0, 0);
    CP_COMMIT();

    #pragma unroll
    for (int c = 0; c < NC; c++) {
        if (c + 1 < NC) {
            load_chunk(c + 1, (c + 1) & 1);
            CP_COMMIT();
            CP_WAIT(1);
        } else {
            CP_WAIT(0);
        }
        __syncthreads();

        const uint32_t sA = sbase + (uint32_t)((c & 1) * STAGE);
        const uint32_t sB = sA + 2 * ABYTES;
        #pragma unroll
        for (int ks = 0; ks < BK / 16; ks++) {
            const uint32_t kg = 2 * ks;
            uint32_t ah[2][4], al[2][4], bh[2][4], bl[2][4];
            #pragma unroll
            for (int mt = 0; mt < 2; mt++) {
                const uint32_t addr = sA + aOff[mt] + ((kg + aDg) ^ swA) * 16u;
                LDSM4(ah[mt], addr);
                LDSM4(al[mt], addr + (uint32_t)ABYTES);
            }
            #pragma unroll
            for (int np = 0; np < 2; np++) {
                const uint32_t addr = sB + bOff[np] + ((kg + bDg) ^ swB) * 16u;
                LDSM4(bh[np], addr);
                LDSM4(bl[np], addr + (uint32_t)BBYTES);
            }
            #pragma unroll
            for (int mt = 0; mt < 2; mt++)
                #pragma unroll
                for (int np = 0; np < 2; np++)
                    #pragma unroll
                    for (int h = 0; h < 2; h++) {
                        float* d = acc[mt][np * 2 + h];
                        MMA_BF16(d, ah[mt], bh[np][2 * h], bh[np][2 * h + 1]);
                        MMA_BF16(d, al[mt], bh[np][2 * h], bh[np][2 * h + 1]);
                        MMA_BF16(d, ah[mt], bl[np][2 * h], bl[np][2 * h + 1]);
                    }
        }
        __syncthreads();
    }

    const int g  = lane >> 2;
    const int tg = lane & 3;
    #pragma unroll
    for (int nt = 0; nt < 4; nt++) {
        const int col = j0 + wn * 32 + nt * 8 + tg * 2;
        const float b0 = bias[col], b1 = bias[col + 1];
        #pragma unroll
        for (int mt = 0; mt < 2; mt++) {
            const float* d = acc[mt][nt];
            const int r0 = row0 + wm * 32 + mt * 16 + g;
            if (r0 < Nrows) {
                float2 v = make_float2(d[0] + b0, d[1] + b1);
                if (RELU) { v.x = fmaxf(v.x, 0.f); v.y = fmaxf(v.y, 0.f); }
                *(float2*)(C + (size_t)r0 * JD + col) = v;
            }
            const int r1 = r0 + 8;
            if (r1 < Nrows) {
                float2 v = make_float2(d[2] + b0, d[3] + b1);
                if (RELU) { v.x = fmaxf(v.x, 0.f); v.y = fmaxf(v.y, 0.f); }
                *(float2*)(C + (size_t)r1 * JD + col) = v;
            }
        }
    }
}

// ============================ attention =====================================
// One warp per node, single pass, no smem, unshifted softmax (|p| small).
// Exact R11 loop (best measured attention variant).
// Output H written directly as pre-split bf16 hi/lo planes for GEMM2.
__global__ __launch_bounds__(256)
void attn_kernel(const float* __restrict__ x, const float* __restrict__ ts,
                 const int* __restrict__ idx,
                 const float* __restrict__ w0p, const float* __restrict__ b0p,
                 const float* __restrict__ Wt, const float* __restrict__ Bt,
                 const float* __restrict__ A, int N)
{
    const int wid  = threadIdx.x >> 5;
    const int lane = threadIdx.x & 31;
    const int n    = blockIdx.x * 8 + wid;
    if (n >= N) return;

    int   m_l = 0;
    float t_l = 0.f;
    if (lane < KNBR) {
        m_l = idx[n * KNBR + lane];
        t_l = ts [n * KNBR + lane];
    }

    const float* Arow = A + (size_t)n * FD;
    const float4 aX  = *(const float4*)(Arow + lane * 4);
    const float  aT0 = Arow[INF + lane];
    const float  aT1 = Arow[INF + 32 + lane];

    float w_a, b_a;
    if (lane == 0) { w_a = w0p[0]; b_a = b0p[0]; }
    else           { w_a = Wt[lane - 1]; b_a = Bt[lane - 1]; }
    const float w_b = Wt[lane + 31];
    const float b_b = Bt[lane + 31];

    float lsum = 0.f;
    float4 acc = make_float4(0.f, 0.f, 0.f, 0.f);
    float at0 = 0.f, at1 = 0.f;

    #pragma unroll
    for (int k = 0; k < KNBR; k++) {
        const int   m = __shfl_sync(0xffffffffu, m_l, k);
        const float t = __shfl_sync(0xffffffffu, t_l, k);
        const float4 xv = *(const float4*)(x + (size_t)m * INF + lane * 4);

        float va = fmaf(t, w_a, b_a);
        if (lane != 0) va = __sinf(va);
        const float vb = __sinf(fmaf(t, w_b, b_b));

        float p = xv.x * aX.x;
        p = fmaf(xv.y, aX.y, p);
        p = fmaf(xv.z, aX.z, p);
        p = fmaf(xv.w, aX.w, p);
        p = fmaf(va, aT0, p);
        p = fmaf(vb, aT1, p);
        #pragma unroll
        for (int o = 16; o > 0; o >>= 1) p += __shfl_xor_sync(0xffffffffu, p, o);

        const float e = __expf(p);   // |p| small: no max shift needed
        lsum += e;
        acc.x = fmaf(e, xv.x, acc.x);
        acc.y = fmaf(e, xv.y, acc.y);
        acc.z = fmaf(e, xv.z, acc.z);
        acc.w = fmaf(e, xv.w, acc.w);
        at0 = fmaf(e, va, at0);
        at1 = fmaf(e, vb, at1);
    }

    const float inv = 1.0f / lsum;
    __nv_bfloat16* hh = g_Hhi + (size_t)n * FD;
    __nv_bfloat16* hl = g_Hlo + (size_t)n * FD;

    uint32_t h0, l0, h1, l1;
    split2(acc.x * inv, acc.y * inv, h0, l0);
    split2(acc.z * inv, acc.w * inv, h1, l1);
    *(uint2*)(hh + lane * 4) = make_uint2(h0, h1);
    *(uint2*)(hl + lane * 4) = make_uint2(l0, l1);

    {
        const float v0 = at0 * inv;
        const __nv_bfloat16 hv = __float2bfloat16(v0);
        hh[INF + lane] = hv;
        hl[INF + lane] = __float2bfloat16(v0 - __bfloat162float(hv));
    }
    {
        const float v1 = at1 * inv;
        const __nv_bfloat16 hv = __float2bfloat16(v1);
        hh[INF + 32 + lane] = hv;
        hl[INF + 32 + lane] = __float2bfloat16(v1 - __bfloat162float(hv));
    }
}

// ============================ launch ========================================
// Input order: x, ts, idx, t2v_w0, t2v_b0, t2v_W, t2v_B, Wq, Wk, Wv, Wo, bo
extern "C" void kernel_launch(void* const* d_in, const int* in_sizes, int n_in,
                              void* d_out, int out_size)
{
    const float* x   = (const float*)d_in[0];
    const float* ts  = (const float*)d_in[1];
    const int*   idx = (const int*)  d_in[2];
    const float* w0  = (const float*)d_in[3];
    const float* b0  = (const float*)d_in[4];
    const float* Wt  = (const float*)d_in[5];
    const float* Bt  = (const float*)d_in[6];
    const float* Wq  = (const float*)d_in[7];
    const float* Wk  = (const float*)d_in[8];
    const float* Wv  = (const float*)d_in[9];
    const float* Wo  = (const float*)d_in[10];
    const float* bo  = (const float*)d_in[11];
    float* out = (float*)d_out;

    const int N     = in_sizes[0] / INF;
    const int tiles = (N + 127) / 128;

    void *pC, *pA, *pXh, *pXl, *pHh, *pHl, *pB1h, *pB1l, *pB2h, *pB2l;
    cudaGetSymbolAddress(&pC,   g_c);
    cudaGetSymbolAddress(&pA,   g_A);
    cudaGetSymbolAddress(&pXh,  g_Xhi);
    cudaGetSymbolAddress(&pXl,  g_Xlo);
    cudaGetSymbolAddress(&pHh,  g_Hhi);
    cudaGetSymbolAddress(&pHl,  g_Hlo);
    cudaGetSymbolAddress(&pB1h, g_B1hi);
    cudaGetSymbolAddress(&pB1l, g_B1lo);
    cudaGetSymbolAddress(&pB2h, g_B2hi);
    cudaGetSymbolAddress(&pB2l, g_B2lo);

    const int SMEM  = 2 * (2 * (128 * 32 * 2) + 2 * (64 * 32 * 2));  // 49152
    const int PSMEM = INF * WQS * 4;                                 // 66048
    cudaFuncSetAttribute(mma_gemm<128, 192, 0>,
                         cudaFuncAttributeMaxDynamicSharedMemorySize, SMEM);
    cudaFuncSetAttribute(mma_gemm<192, 128, 1>,
                         cudaFuncAttributeMaxDynamicSharedMemorySize, SMEM);
    cudaFuncSetAttribute(init_kernel,
                         cudaFuncAttributeMaxDynamicSharedMemorySize, PSMEM);

    // 1) fused init: prep (CTAs 0..191) + convert_x (CTAs 192..)
    {
        const int count4 = N * (INF / 4);
        init_kernel<<<FD + CONV_CTAS, HD, PSMEM>>>(
            Wq, Wk, Wv, Wo, w0, b0, Wt, Bt, x, count4);
    }

    // 2) A = x @ M + c        (128->192, HMMA cp.async)
    {
        dim3 grid(FD / 64, tiles);
        mma_gemm<128, 192, 0><<<grid, 256, SMEM>>>(
            (const __nv_bfloat16*)pXh, (const __nv_bfloat16*)pXl,
            (const __nv_bfloat16*)pB1h, (const __nv_bfloat16*)pB1l,
            (const float*)pC, (float*)pA, N);
    }

    // 3) attention -> H planes (warp per node, 8 nodes/CTA)
    attn_kernel<<<(N + 7) / 8, 256>>>(x, ts, idx, w0, b0, Wt, Bt,
                                      (const float*)pA, N);

    // 4) out = relu(H @ Wvo + bo)   (192->128, HMMA cp.async)
    {
        dim3 grid(HD / 64, tiles);
        mma_gemm<192, 128, 1><<<grid, 256, SMEM>>>(
            (const __nv_bfloat16*)pHh, (const __nv_bfloat16*)pHl,
            (const __nv_bfloat16*)pB2h, (const __nv_bfloat16*)pB2l,
            bo, out, N);
    }
}